// round 13
// baseline (speedup 1.0000x reference)
#include <cuda_runtime.h>

#define BB 2
#define SS 2048
#define DIN 1024
#define HH 16
#define DD 64
#define MTOT (BB*SS)

// Scratch (allocation-free rule: __device__ globals)
__device__ float g_Q[BB*HH*SS*DD];    // [b][h][s][d]
__device__ float g_K[BB*HH*SS*DD];
__device__ float g_V[BB*HH*SS*DD];
__device__ float g_ctx[MTOT*HH*DD];   // [b][s][h*64+d]

// ---------------------------------------------------------------------------
// TF32 helpers
// ---------------------------------------------------------------------------
__device__ __forceinline__ unsigned f2tf(float f) {
    unsigned r;
    asm("cvt.rna.tf32.f32 %0, %1;" : "=r"(r) : "f"(f));
    return r;
}

__device__ __forceinline__ void mma_tf32(float c[4],
    unsigned a0, unsigned a1, unsigned a2, unsigned a3,
    unsigned b0, unsigned b1)
{
    asm volatile(
        "mma.sync.aligned.m16n8k8.row.col.f32.tf32.tf32.f32 "
        "{%0,%1,%2,%3}, {%4,%5,%6,%7}, {%8,%9}, {%0,%1,%2,%3};"
        : "+f"(c[0]), "+f"(c[1]), "+f"(c[2]), "+f"(c[3])
        : "r"(a0), "r"(a1), "r"(a2), "r"(a3), "r"(b0), "r"(b1));
}

// Shared mainloop: acc += A(m0:+128, :) @ B(n0:+128, :)^T, K=1024, tf32.
// As/Bs layout [row][36] (pad 4): STS.128 staging conflict-free, fragment
// LDS bank = (4*row + k) % 32 conflict-free.
__device__ __forceinline__ void tf32_mainloop(
    const float* __restrict__ Ag, const float* __restrict__ Bg,
    int m0, int n0, int tid,
    unsigned (*As)[36], unsigned (*Bs)[36],
    float acc[4][4][4])
{
    const int lane = tid & 31, wid = tid >> 5;
    const int wm = wid >> 2, wn = wid & 3;      // warp 64x32 region
    const int g = lane >> 2, t = lane & 3;
    const int srow = tid >> 3;                  // 0..31
    const int skq = (tid & 7) * 4;              // 0..28

    for (int kt = 0; kt < DIN; kt += 32) {
#pragma unroll
        for (int it = 0; it < 4; it++) {
            int row = srow + it * 32;
            float4 a = *(const float4*)&Ag[(m0 + row) * DIN + kt + skq];
            float4 b = *(const float4*)&Bg[(n0 + row) * DIN + kt + skq];
            *(uint4*)&As[row][skq] = make_uint4(f2tf(a.x), f2tf(a.y), f2tf(a.z), f2tf(a.w));
            *(uint4*)&Bs[row][skq] = make_uint4(f2tf(b.x), f2tf(b.y), f2tf(b.z), f2tf(b.w));
        }
        __syncthreads();
#pragma unroll
        for (int ks = 0; ks < 4; ks++) {
            const int k0 = ks * 8;
            unsigned af[4][4], bf[4][2];
#pragma unroll
            for (int mt = 0; mt < 4; mt++) {
                int mr = wm * 64 + mt * 16 + g;
                af[mt][0] = As[mr][k0 + t];
                af[mt][1] = As[mr + 8][k0 + t];
                af[mt][2] = As[mr][k0 + t + 4];
                af[mt][3] = As[mr + 8][k0 + t + 4];
            }
#pragma unroll
            for (int nt = 0; nt < 4; nt++) {
                int nc = wn * 32 + nt * 8 + g;
                bf[nt][0] = Bs[nc][k0 + t];
                bf[nt][1] = Bs[nc][k0 + t + 4];
            }
#pragma unroll
            for (int mt = 0; mt < 4; mt++)
#pragma unroll
                for (int nt = 0; nt < 4; nt++)
                    mma_tf32(acc[mt][nt], af[mt][0], af[mt][1], af[mt][2], af[mt][3],
                             bf[nt][0], bf[nt][1]);
        }
        __syncthreads();
    }
}

// ---------------------------------------------------------------------------
// QKV projection (TF32 tensor cores), scatter into [b][h][s][d]
// ---------------------------------------------------------------------------
__global__ __launch_bounds__(256) void qkv_gemm(
    const float* __restrict__ X,
    const float* __restrict__ Wq,
    const float* __restrict__ Wk,
    const float* __restrict__ Wv)
{
    __shared__ unsigned As[128][36];
    __shared__ unsigned Bs[128][36];

    const int nblk = blockIdx.x;
    const int which = nblk >> 3;
    const float* W = (which == 0) ? Wq : (which == 1 ? Wk : Wv);
    float* Dst = (which == 0) ? g_Q : (which == 1 ? g_K : g_V);
    const int n0 = (nblk & 7) * 128;
    const int m0 = blockIdx.y * 128;

    const int tid = threadIdx.x;
    const int lane = tid & 31, wid = tid >> 5;
    const int wm = wid >> 2, wn = wid & 3;
    const int g = lane >> 2, t = lane & 3;

    float acc[4][4][4] = {};
    tf32_mainloop(X, W, m0, n0, tid, As, Bs, acc);

#pragma unroll
    for (int mt = 0; mt < 4; mt++) {
        int m = m0 + wm * 64 + mt * 16 + g;
        int b = m >> 11, s = m & (SS - 1);
#pragma unroll
        for (int nt = 0; nt < 4; nt++) {
            int n = n0 + wn * 32 + nt * 8 + 2 * t;
            int h = n >> 6, d = n & 63;
            float* dst = &Dst[(((b * HH + h) * SS) + s) * DD + d];
            *(float2*)dst = make_float2(acc[mt][nt][0], acc[mt][nt][1]);
            *(float2*)(dst + 8 * DD) = make_float2(acc[mt][nt][2], acc[mt][nt][3]);
        }
    }
}

// ---------------------------------------------------------------------------
// Output projection (TF32): out = ctx @ Wo^T + bo
// ---------------------------------------------------------------------------
__global__ __launch_bounds__(256) void out_gemm(
    const float* __restrict__ Wo,
    const float* __restrict__ bo,
    float* __restrict__ out)
{
    __shared__ unsigned As[128][36];
    __shared__ unsigned Bs[128][36];

    const int n0 = blockIdx.x * 128;
    const int m0 = blockIdx.y * 128;

    const int tid = threadIdx.x;
    const int lane = tid & 31, wid = tid >> 5;
    const int wm = wid >> 2, wn = wid & 3;
    const int g = lane >> 2, t = lane & 3;

    float acc[4][4][4] = {};
    tf32_mainloop(g_ctx, Wo, m0, n0, tid, As, Bs, acc);

#pragma unroll
    for (int nt = 0; nt < 4; nt++) {
        int n = n0 + wn * 32 + nt * 8 + 2 * t;
        float2 bias = *(const float2*)&bo[n];
#pragma unroll
        for (int mt = 0; mt < 4; mt++) {
            int m = m0 + wm * 64 + mt * 16 + g;
            *(float2*)&out[m * 1024 + n] =
                make_float2(acc[mt][nt][0] + bias.x, acc[mt][nt][1] + bias.y);
            *(float2*)&out[(m + 8) * 1024 + n] =
                make_float2(acc[mt][nt][2] + bias.x, acc[mt][nt][3] + bias.y);
        }
    }
}

// ---------------------------------------------------------------------------
// Flash attention fp32, causal (unchanged from R11).
// ---------------------------------------------------------------------------
#define ATTN_SMEM ((64*65 + 64*65 + 64*64 + 64*65) * 4)

__global__ __launch_bounds__(256) void flash_attn()
{
    extern __shared__ float sm[];
    float* Qt = sm;
    float* Kt = Qt + 64 * 65;
    float* Vs = Kt + 64 * 65;
    float* Ps = Vs + 64 * 64;

    const int bh = blockIdx.y;
    const int qt = 31 - blockIdx.x;   // longest-job-first
    const float* Qg = g_Q + bh * SS * DD;
    const float* Kg = g_K + bh * SS * DD;
    const float* Vg = g_V + bh * SS * DD;

    const int tid = threadIdx.x;
    const int tx = tid & 15, ty = tid >> 4;
    const int q0 = qt * 64;

#pragma unroll
    for (int it = 0; it < 4; it++) {
        int idx = tid + it * 256;
        int r = idx >> 4;
        int d0 = (idx & 15) * 4;
        float4 v = *(const float4*)&Qg[(q0 + r) * DD + d0];
        Qt[(d0 + 0) * 65 + r] = v.x;
        Qt[(d0 + 1) * 65 + r] = v.y;
        Qt[(d0 + 2) * 65 + r] = v.z;
        Qt[(d0 + 3) * 65 + r] = v.w;
    }

    float m_i[4], l_i[4], o[4][4];
#pragma unroll
    for (int i = 0; i < 4; i++) {
        m_i[i] = -1e30f; l_i[i] = 0.f;
#pragma unroll
        for (int j = 0; j < 4; j++) o[i][j] = 0.f;
    }

    for (int jt = 0; jt <= qt; jt++) {
#pragma unroll
        for (int it = 0; it < 4; it++) {
            int idx = tid + it * 256;
            int r = idx >> 4;
            int d0 = (idx & 15) * 4;
            float4 kv = *(const float4*)&Kg[(jt * 64 + r) * DD + d0];
            Kt[(d0 + 0) * 65 + r] = kv.x;
            Kt[(d0 + 1) * 65 + r] = kv.y;
            Kt[(d0 + 2) * 65 + r] = kv.z;
            Kt[(d0 + 3) * 65 + r] = kv.w;
            float4 vv = *(const float4*)&Vg[(jt * 64 + r) * DD + d0];
            *(float4*)&Vs[r * 64 + d0] = vv;
        }
        __syncthreads();

        float s[4][4] = {};
#pragma unroll
        for (int k = 0; k < 64; k++) {
            float ra[4], rb[4];
#pragma unroll
            for (int i = 0; i < 4; i++) ra[i] = Qt[k * 65 + ty * 4 + i];
#pragma unroll
            for (int j = 0; j < 4; j++) rb[j] = Kt[k * 65 + tx * 4 + j];
#pragma unroll
            for (int i = 0; i < 4; i++)
#pragma unroll
                for (int j = 0; j < 4; j++) s[i][j] += ra[i] * rb[j];
        }
#pragma unroll
        for (int i = 0; i < 4; i++)
#pragma unroll
            for (int j = 0; j < 4; j++) s[i][j] *= 0.125f;

        if (jt == qt) {
#pragma unroll
            for (int i = 0; i < 4; i++) {
                int r = ty * 4 + i;
#pragma unroll
                for (int j = 0; j < 4; j++) {
                    int c = tx * 4 + j;
                    if (c > r) s[i][j] = -1e30f;
                }
            }
        }

        float alpha[4];
#pragma unroll
        for (int i = 0; i < 4; i++) {
            float lm = fmaxf(fmaxf(s[i][0], s[i][1]), fmaxf(s[i][2], s[i][3]));
#pragma unroll
            for (int msk = 1; msk < 16; msk <<= 1)
                lm = fmaxf(lm, __shfl_xor_sync(0xffffffffu, lm, msk));
            float mn = fmaxf(m_i[i], lm);
            alpha[i] = __expf(m_i[i] - mn);
            m_i[i] = mn;
            float rs = 0.f;
#pragma unroll
            for (int j = 0; j < 4; j++) {
                float p = __expf(s[i][j] - mn);
                s[i][j] = p;
                rs += p;
            }
#pragma unroll
            for (int msk = 1; msk < 16; msk <<= 1)
                rs += __shfl_xor_sync(0xffffffffu, rs, msk);
            l_i[i] = l_i[i] * alpha[i] + rs;
#pragma unroll
            for (int j = 0; j < 4; j++) o[i][j] *= alpha[i];
        }

#pragma unroll
        for (int i = 0; i < 4; i++)
#pragma unroll
            for (int j = 0; j < 4; j++)
                Ps[(tx * 4 + j) * 65 + ty * 4 + i] = s[i][j];
        __syncthreads();

#pragma unroll
        for (int k = 0; k < 64; k++) {
            float pa[4], vb[4];
#pragma unroll
            for (int i = 0; i < 4; i++) pa[i] = Ps[k * 65 + ty * 4 + i];
#pragma unroll
            for (int j = 0; j < 4; j++) vb[j] = Vs[k * 64 + tx * 4 + j];
#pragma unroll
            for (int i = 0; i < 4; i++)
#pragma unroll
                for (int j = 0; j < 4; j++) o[i][j] += pa[i] * vb[j];
        }
        __syncthreads();
    }

    const int b = bh >> 4, h = bh & 15;
#pragma unroll
    for (int i = 0; i < 4; i++) {
        float inv = 1.0f / l_i[i];
        int srow = q0 + ty * 4 + i;
#pragma unroll
        for (int j = 0; j < 4; j++) {
            int d = tx * 4 + j;
            g_ctx[(b * SS + srow) * (HH * DD) + h * DD + d] = o[i][j] * inv;
        }
    }
}

// ---------------------------------------------------------------------------
extern "C" void kernel_launch(void* const* d_in, const int* in_sizes, int n_in,
                              void* d_out, int out_size)
{
    const float* x  = (const float*)d_in[0];
    const float* wq = (const float*)d_in[2];
    const float* wk = (const float*)d_in[3];
    const float* wv = (const float*)d_in[4];
    const float* wo = (const float*)d_in[5];
    const float* bo = (const float*)d_in[6];
    float* out = (float*)d_out;

    cudaFuncSetAttribute(flash_attn,
                         cudaFuncAttributeMaxDynamicSharedMemorySize, ATTN_SMEM);

    qkv_gemm<<<dim3(24, 32), 256>>>(x, wq, wk, wv);
    flash_attn<<<dim3(32, 32), 256, ATTN_SMEM>>>();
    out_gemm<<<dim3(8, 32), 256>>>(wo, bo, out);
}

// round 14
// speedup vs baseline: 1.7845x; 1.7845x over previous
#include <cuda_runtime.h>

#define BB 2
#define SS 2048
#define DIN 1024
#define HH 16
#define DD 64
#define MTOT (BB*SS)

__device__ float g_Q[BB*HH*SS*DD];    // [b][h][s][d]
__device__ float g_K[BB*HH*SS*DD];
__device__ float g_V[BB*HH*SS*DD];
__device__ float g_ctx[MTOT*HH*DD];   // [b][s][h*64+d]

// ---------------------------------------------------------------------------
// TF32 helpers
// ---------------------------------------------------------------------------
__device__ __forceinline__ unsigned f2tf(float f) {
    unsigned r;
    asm("cvt.rna.tf32.f32 %0, %1;" : "=r"(r) : "f"(f));
    return r;
}

__device__ __forceinline__ void mma_tf32(float c[4],
    unsigned a0, unsigned a1, unsigned a2, unsigned a3,
    unsigned b0, unsigned b1)
{
    asm volatile(
        "mma.sync.aligned.m16n8k8.row.col.f32.tf32.tf32.f32 "
        "{%0,%1,%2,%3}, {%4,%5,%6,%7}, {%8,%9}, {%0,%1,%2,%3};"
        : "+f"(c[0]), "+f"(c[1]), "+f"(c[2]), "+f"(c[3])
        : "r"(a0), "r"(a1), "r"(a2), "r"(a3), "r"(b0), "r"(b1));
}

// ---------------------------------------------------------------------------
// Shared TF32 GEMM mainloop (unchanged from R13)
// ---------------------------------------------------------------------------
__device__ __forceinline__ void tf32_mainloop(
    const float* __restrict__ Ag, const float* __restrict__ Bg,
    int m0, int n0, int tid,
    unsigned (*As)[36], unsigned (*Bs)[36],
    float acc[4][4][4])
{
    const int lane = tid & 31, wid = tid >> 5;
    const int wm = wid >> 2, wn = wid & 3;
    const int g = lane >> 2, t = lane & 3;
    const int srow = tid >> 3;
    const int skq = (tid & 7) * 4;

    for (int kt = 0; kt < DIN; kt += 32) {
#pragma unroll
        for (int it = 0; it < 4; it++) {
            int row = srow + it * 32;
            float4 a = *(const float4*)&Ag[(m0 + row) * DIN + kt + skq];
            float4 b = *(const float4*)&Bg[(n0 + row) * DIN + kt + skq];
            *(uint4*)&As[row][skq] = make_uint4(f2tf(a.x), f2tf(a.y), f2tf(a.z), f2tf(a.w));
            *(uint4*)&Bs[row][skq] = make_uint4(f2tf(b.x), f2tf(b.y), f2tf(b.z), f2tf(b.w));
        }
        __syncthreads();
#pragma unroll
        for (int ks = 0; ks < 4; ks++) {
            const int k0 = ks * 8;
            unsigned af[4][4], bf[4][2];
#pragma unroll
            for (int mt = 0; mt < 4; mt++) {
                int mr = wm * 64 + mt * 16 + g;
                af[mt][0] = As[mr][k0 + t];
                af[mt][1] = As[mr + 8][k0 + t];
                af[mt][2] = As[mr][k0 + t + 4];
                af[mt][3] = As[mr + 8][k0 + t + 4];
            }
#pragma unroll
            for (int nt = 0; nt < 4; nt++) {
                int nc = wn * 32 + nt * 8 + g;
                bf[nt][0] = Bs[nc][k0 + t];
                bf[nt][1] = Bs[nc][k0 + t + 4];
            }
#pragma unroll
            for (int mt = 0; mt < 4; mt++)
#pragma unroll
                for (int nt = 0; nt < 4; nt++)
                    mma_tf32(acc[mt][nt], af[mt][0], af[mt][1], af[mt][2], af[mt][3],
                             bf[nt][0], bf[nt][1]);
        }
        __syncthreads();
    }
}

// ---------------------------------------------------------------------------
// QKV projection (TF32), scatter into [b][h][s][d]
// ---------------------------------------------------------------------------
__global__ __launch_bounds__(256) void qkv_gemm(
    const float* __restrict__ X,
    const float* __restrict__ Wq,
    const float* __restrict__ Wk,
    const float* __restrict__ Wv)
{
    __shared__ unsigned As[128][36];
    __shared__ unsigned Bs[128][36];

    const int nblk = blockIdx.x;
    const int which = nblk >> 3;
    const float* W = (which == 0) ? Wq : (which == 1 ? Wk : Wv);
    float* Dst = (which == 0) ? g_Q : (which == 1 ? g_K : g_V);
    const int n0 = (nblk & 7) * 128;
    const int m0 = blockIdx.y * 128;

    const int tid = threadIdx.x;
    const int lane = tid & 31, wid = tid >> 5;
    const int wm = wid >> 2, wn = wid & 3;
    const int g = lane >> 2, t = lane & 3;

    float acc[4][4][4] = {};
    tf32_mainloop(X, W, m0, n0, tid, As, Bs, acc);

#pragma unroll
    for (int mt = 0; mt < 4; mt++) {
        int m = m0 + wm * 64 + mt * 16 + g;
        int b = m >> 11, s = m & (SS - 1);
#pragma unroll
        for (int nt = 0; nt < 4; nt++) {
            int n = n0 + wn * 32 + nt * 8 + 2 * t;
            int h = n >> 6, d = n & 63;
            float* dst = &Dst[(((b * HH + h) * SS) + s) * DD + d];
            *(float2*)dst = make_float2(acc[mt][nt][0], acc[mt][nt][1]);
            *(float2*)(dst + 8 * DD) = make_float2(acc[mt][nt][2], acc[mt][nt][3]);
        }
    }
}

// ---------------------------------------------------------------------------
// Output projection (TF32): out = ctx @ Wo^T + bo
// ---------------------------------------------------------------------------
__global__ __launch_bounds__(256) void out_gemm(
    const float* __restrict__ Wo,
    const float* __restrict__ bo,
    float* __restrict__ out)
{
    __shared__ unsigned As[128][36];
    __shared__ unsigned Bs[128][36];

    const int n0 = blockIdx.x * 128;
    const int m0 = blockIdx.y * 128;

    const int tid = threadIdx.x;
    const int lane = tid & 31, wid = tid >> 5;
    const int wm = wid >> 2, wn = wid & 3;
    const int g = lane >> 2, t = lane & 3;

    float acc[4][4][4] = {};
    tf32_mainloop(g_ctx, Wo, m0, n0, tid, As, Bs, acc);

#pragma unroll
    for (int nt = 0; nt < 4; nt++) {
        int n = n0 + wn * 32 + nt * 8 + 2 * t;
        float2 bias = *(const float2*)&bo[n];
#pragma unroll
        for (int mt = 0; mt < 4; mt++) {
            int m = m0 + wm * 64 + mt * 16 + g;
            *(float2*)&out[m * 1024 + n] =
                make_float2(acc[mt][nt][0] + bias.x, acc[mt][nt][1] + bias.y);
            *(float2*)&out[(m + 8) * 1024 + n] =
                make_float2(acc[mt][nt][2] + bias.x, acc[mt][nt][3] + bias.y);
        }
    }
}

// ---------------------------------------------------------------------------
// Flash attention, TF32 tensor cores. Br=128, Bc=64, 256 threads.
// Warp w owns Q rows [w*16, w*16+16) -> S/P warp-private.
// Smem tiles [row][68]: fragment LDS bank = 4g+t (conflict-free for Q/K/P).
// ---------------------------------------------------------------------------
#define BR 128
#define BC 64
#define FST 68
#define ATTN_SMEM ((BR*FST + 2*BC*FST + BR*FST) * 4)   // Qs, Ks, Vs, Ps = 104448

__global__ __launch_bounds__(256, 2) void flash_attn()
{
    extern __shared__ unsigned smu[];
    unsigned (*Qs)[FST] = (unsigned(*)[FST])smu;
    unsigned (*Ks)[FST] = (unsigned(*)[FST])(smu + BR * FST);
    unsigned (*Vs)[FST] = (unsigned(*)[FST])(smu + (BR + BC) * FST);
    unsigned (*Ps)[FST] = (unsigned(*)[FST])(smu + (BR + 2 * BC) * FST);

    const int bh = blockIdx.y;
    const int qt = (SS / BR - 1) - blockIdx.x;   // longest-job-first
    const int q0 = qt * BR;
    const float* Qg = g_Q + bh * SS * DD;
    const float* Kg = g_K + bh * SS * DD;
    const float* Vg = g_V + bh * SS * DD;

    const int tid = threadIdx.x;
    const int lane = tid & 31, w = tid >> 5;
    const int g = lane >> 2, t = lane & 3;
    const int wr = w * 16;

    // stage Q (pre-scaled by 0.125) as tf32
#pragma unroll
    for (int it = 0; it < 8; it++) {
        int idx = tid + it * 256;
        int r = idx >> 4, d0 = (idx & 15) * 4;
        float4 v = *(const float4*)&Qg[(q0 + r) * DD + d0];
        *(uint4*)&Qs[r][d0] = make_uint4(f2tf(0.125f * v.x), f2tf(0.125f * v.y),
                                         f2tf(0.125f * v.z), f2tf(0.125f * v.w));
    }

    float oacc[8][4] = {};
    float m0 = -1e30f, m1 = -1e30f, l0 = 0.f, l1 = 0.f;

    const int jmax = 2 * qt + 1;
    for (int jt = 0; jt <= jmax; jt++) {
        const int j0 = jt * BC;
        __syncthreads();   // prior-iter smem reads done (also covers Q staging)
#pragma unroll
        for (int it = 0; it < 4; it++) {
            int idx = tid + it * 256;
            int r = idx >> 4, d0 = (idx & 15) * 4;
            float4 kv = *(const float4*)&Kg[(j0 + r) * DD + d0];
            *(uint4*)&Ks[r][d0] = make_uint4(f2tf(kv.x), f2tf(kv.y), f2tf(kv.z), f2tf(kv.w));
            float4 vv = *(const float4*)&Vg[(j0 + r) * DD + d0];
            *(uint4*)&Vs[r][d0] = make_uint4(f2tf(vv.x), f2tf(vv.y), f2tf(vv.z), f2tf(vv.w));
        }
        __syncthreads();

        if (j0 <= q0 + wr + 15) {   // warp has at least one unmasked column
            // ---- S = Qw @ K^T (16x64), warp-private
            float sacc[8][4] = {};
#pragma unroll
            for (int ks = 0; ks < 8; ks++) {
                const int k0 = ks * 8;
                unsigned a0 = Qs[wr + g][k0 + t];
                unsigned a1 = Qs[wr + g + 8][k0 + t];
                unsigned a2 = Qs[wr + g][k0 + t + 4];
                unsigned a3 = Qs[wr + g + 8][k0 + t + 4];
#pragma unroll
                for (int nt = 0; nt < 8; nt++) {
                    unsigned b0 = Ks[nt * 8 + g][k0 + t];
                    unsigned b1 = Ks[nt * 8 + g][k0 + t + 4];
                    mma_tf32(sacc[nt], a0, a1, a2, a3, b0, b1);
                }
            }

            // ---- causal mask (only on diagonal-straddling tiles)
            const int r0 = q0 + wr + g, r1 = r0 + 8;
            if (j0 + BC - 1 > q0 + wr) {
#pragma unroll
                for (int nt = 0; nt < 8; nt++) {
                    int c0 = j0 + nt * 8 + 2 * t, c1 = c0 + 1;
                    if (c0 > r0) sacc[nt][0] = -1e30f;
                    if (c1 > r0) sacc[nt][1] = -1e30f;
                    if (c0 > r1) sacc[nt][2] = -1e30f;
                    if (c1 > r1) sacc[nt][3] = -1e30f;
                }
            }

            // ---- online softmax (rows r0, r1; row spread over quad t=0..3)
            float mx0 = -1e30f, mx1 = -1e30f;
#pragma unroll
            for (int nt = 0; nt < 8; nt++) {
                mx0 = fmaxf(mx0, fmaxf(sacc[nt][0], sacc[nt][1]));
                mx1 = fmaxf(mx1, fmaxf(sacc[nt][2], sacc[nt][3]));
            }
            mx0 = fmaxf(mx0, __shfl_xor_sync(0xffffffffu, mx0, 1));
            mx0 = fmaxf(mx0, __shfl_xor_sync(0xffffffffu, mx0, 2));
            mx1 = fmaxf(mx1, __shfl_xor_sync(0xffffffffu, mx1, 1));
            mx1 = fmaxf(mx1, __shfl_xor_sync(0xffffffffu, mx1, 2));
            float mn0 = fmaxf(m0, mx0), mn1 = fmaxf(m1, mx1);
            float a0 = __expf(m0 - mn0), a1 = __expf(m1 - mn1);
            m0 = mn0; m1 = mn1;

            float rs0 = 0.f, rs1 = 0.f;
#pragma unroll
            for (int nt = 0; nt < 8; nt++) {
                float p0 = __expf(sacc[nt][0] - mn0);
                float p1 = __expf(sacc[nt][1] - mn0);
                float p2 = __expf(sacc[nt][2] - mn1);
                float p3 = __expf(sacc[nt][3] - mn1);
                rs0 += p0 + p1; rs1 += p2 + p3;
                *(uint2*)&Ps[wr + g][nt * 8 + 2 * t] = make_uint2(f2tf(p0), f2tf(p1));
                *(uint2*)&Ps[wr + g + 8][nt * 8 + 2 * t] = make_uint2(f2tf(p2), f2tf(p3));
                oacc[nt][0] *= a0; oacc[nt][1] *= a0;
                oacc[nt][2] *= a1; oacc[nt][3] *= a1;
            }
            rs0 += __shfl_xor_sync(0xffffffffu, rs0, 1);
            rs0 += __shfl_xor_sync(0xffffffffu, rs0, 2);
            rs1 += __shfl_xor_sync(0xffffffffu, rs1, 1);
            rs1 += __shfl_xor_sync(0xffffffffu, rs1, 2);
            l0 = l0 * a0 + rs0;
            l1 = l1 * a1 + rs1;

            __syncwarp();   // P visible within warp

            // ---- O += P @ V (16x64 @ 64x64)
#pragma unroll
            for (int ks = 0; ks < 8; ks++) {
                const int k0 = ks * 8;
                unsigned pa0 = Ps[wr + g][k0 + t];
                unsigned pa1 = Ps[wr + g + 8][k0 + t];
                unsigned pa2 = Ps[wr + g][k0 + t + 4];
                unsigned pa3 = Ps[wr + g + 8][k0 + t + 4];
#pragma unroll
                for (int nt = 0; nt < 8; nt++) {
                    unsigned b0 = Vs[k0 + t][nt * 8 + g];
                    unsigned b1 = Vs[k0 + t + 4][nt * 8 + g];
                    mma_tf32(oacc[nt], pa0, pa1, pa2, pa3, b0, b1);
                }
            }
        }
    }

    // ---- finalize: divide by l, write ctx[b][s][h*64+d]
    const int b = bh >> 4, h = bh & 15;
    const float inv0 = 1.0f / l0, inv1 = 1.0f / l1;
    const int r0 = q0 + wr + g, r1 = r0 + 8;
#pragma unroll
    for (int nt = 0; nt < 8; nt++) {
        int col = h * DD + nt * 8 + 2 * t;
        *(float2*)&g_ctx[(b * SS + r0) * (HH * DD) + col] =
            make_float2(oacc[nt][0] * inv0, oacc[nt][1] * inv0);
        *(float2*)&g_ctx[(b * SS + r1) * (HH * DD) + col] =
            make_float2(oacc[nt][2] * inv1, oacc[nt][3] * inv1);
    }
}

// ---------------------------------------------------------------------------
extern "C" void kernel_launch(void* const* d_in, const int* in_sizes, int n_in,
                              void* d_out, int out_size)
{
    const float* x  = (const float*)d_in[0];
    const float* wq = (const float*)d_in[2];
    const float* wk = (const float*)d_in[3];
    const float* wv = (const float*)d_in[4];
    const float* wo = (const float*)d_in[5];
    const float* bo = (const float*)d_in[6];
    float* out = (float*)d_out;

    cudaFuncSetAttribute(flash_attn,
                         cudaFuncAttributeMaxDynamicSharedMemorySize, ATTN_SMEM);

    qkv_gemm<<<dim3(24, 32), 256>>>(x, wq, wk, wv);
    flash_attn<<<dim3(SS / BR, 32), 256, ATTN_SMEM>>>();
    out_gemm<<<dim3(8, 32), 256>>>(wo, bo, out);
}

// round 15
// speedup vs baseline: 1.8352x; 1.0284x over previous
#include <cuda_runtime.h>

#define BB 2
#define SS 2048
#define DIN 1024
#define HH 16
#define DD 64
#define MTOT (BB*SS)

__device__ float g_Q[BB*HH*SS*DD];    // [b][h][s][d]
__device__ float g_K[BB*HH*SS*DD];
__device__ float g_V[BB*HH*SS*DD];
__device__ float g_ctx[MTOT*HH*DD];   // [b][s][h*64+d]

// ---------------------------------------------------------------------------
// TF32 / cp.async helpers
// ---------------------------------------------------------------------------
__device__ __forceinline__ unsigned f2tf(float f) {
    unsigned r;
    asm("cvt.rna.tf32.f32 %0, %1;" : "=r"(r) : "f"(f));
    return r;
}

__device__ __forceinline__ void mma_tf32(float c[4],
    unsigned a0, unsigned a1, unsigned a2, unsigned a3,
    unsigned b0, unsigned b1)
{
    asm volatile(
        "mma.sync.aligned.m16n8k8.row.col.f32.tf32.tf32.f32 "
        "{%0,%1,%2,%3}, {%4,%5,%6,%7}, {%8,%9}, {%0,%1,%2,%3};"
        : "+f"(c[0]), "+f"(c[1]), "+f"(c[2]), "+f"(c[3])
        : "r"(a0), "r"(a1), "r"(a2), "r"(a3), "r"(b0), "r"(b1));
}

__device__ __forceinline__ void cpa16(void* smem_ptr, const void* gmem_ptr) {
    unsigned s = (unsigned)__cvta_generic_to_shared(smem_ptr);
    asm volatile("cp.async.cg.shared.global [%0], [%1], 16;" :: "r"(s), "l"(gmem_ptr));
}
#define CPA_COMMIT()  asm volatile("cp.async.commit_group;" ::: "memory")
#define CPA_WAIT(N)   asm volatile("cp.async.wait_group %0;" :: "n"(N) : "memory")

// ---------------------------------------------------------------------------
// TF32 GEMM mainloop: cp.async double-buffered, consumer-side tf32 convert.
// acc += A(m0:+128,:) @ B(n0:+128,:)^T, K=1024.
// Dynamic smem: As[2][128][36] floats, then Bs[2][128][36].
// ---------------------------------------------------------------------------
#define NT (DIN/32)
#define GEMM_SMEM (2*2*128*36*4)   // 73728 B

__device__ __forceinline__ void tf32_mainloop(
    const float* __restrict__ Ag, const float* __restrict__ Bg,
    int m0, int n0, int tid,
    float (*As)[36], float (*Bs)[36],     // 256 rows each (2 buffers of 128)
    float acc[4][4][4])
{
    const int lane = tid & 31, wid = tid >> 5;
    const int wm = wid >> 2, wn = wid & 3;
    const int g = lane >> 2, t = lane & 3;
    const int srow = tid >> 3;             // 0..31
    const int skq = (tid & 7) * 4;         // 0,4,..,28

    // stage tile 0 into buffer 0
#pragma unroll
    for (int it = 0; it < 4; it++) {
        int row = srow + it * 32;
        cpa16(&As[row][skq], &Ag[(m0 + row) * DIN + skq]);
        cpa16(&Bs[row][skq], &Bg[(n0 + row) * DIN + skq]);
    }
    CPA_COMMIT();

    for (int i = 0; i < NT; i++) {
        float (*Ab)[36] = As + (i & 1) * 128;
        float (*Bb)[36] = Bs + (i & 1) * 128;

        if (i + 1 < NT) {
            float (*An)[36] = As + ((i + 1) & 1) * 128;
            float (*Bn)[36] = Bs + ((i + 1) & 1) * 128;
            const int kt = (i + 1) * 32;
#pragma unroll
            for (int it = 0; it < 4; it++) {
                int row = srow + it * 32;
                cpa16(&An[row][skq], &Ag[(m0 + row) * DIN + kt + skq]);
                cpa16(&Bn[row][skq], &Bg[(n0 + row) * DIN + kt + skq]);
            }
            CPA_COMMIT();
            CPA_WAIT(1);     // buffer i ready; buffer i+1 still in flight
        } else {
            CPA_WAIT(0);
        }
        __syncthreads();

#pragma unroll
        for (int ks = 0; ks < 4; ks++) {
            const int k0 = ks * 8;
            unsigned af[4][4], bf[4][2];
#pragma unroll
            for (int mt = 0; mt < 4; mt++) {
                int mr = wm * 64 + mt * 16 + g;
                af[mt][0] = f2tf(Ab[mr][k0 + t]);
                af[mt][1] = f2tf(Ab[mr + 8][k0 + t]);
                af[mt][2] = f2tf(Ab[mr][k0 + t + 4]);
                af[mt][3] = f2tf(Ab[mr + 8][k0 + t + 4]);
            }
#pragma unroll
            for (int nt = 0; nt < 4; nt++) {
                int nc = wn * 32 + nt * 8 + g;
                bf[nt][0] = f2tf(Bb[nc][k0 + t]);
                bf[nt][1] = f2tf(Bb[nc][k0 + t + 4]);
            }
#pragma unroll
            for (int mt = 0; mt < 4; mt++)
#pragma unroll
                for (int nt = 0; nt < 4; nt++)
                    mma_tf32(acc[mt][nt], af[mt][0], af[mt][1], af[mt][2], af[mt][3],
                             bf[nt][0], bf[nt][1]);
        }
        __syncthreads();     // compute done before next iter overwrites buf (i+1)&1... (2-stage)
    }
}

// ---------------------------------------------------------------------------
// QKV projection (TF32), scatter into [b][h][s][d]
// ---------------------------------------------------------------------------
__global__ __launch_bounds__(256, 2) void qkv_gemm(
    const float* __restrict__ X,
    const float* __restrict__ Wq,
    const float* __restrict__ Wk,
    const float* __restrict__ Wv)
{
    extern __shared__ float gsm[];
    float (*As)[36] = (float(*)[36])gsm;
    float (*Bs)[36] = (float(*)[36])(gsm + 2 * 128 * 36);

    const int nblk = blockIdx.x;
    const int which = nblk >> 3;
    const float* W = (which == 0) ? Wq : (which == 1 ? Wk : Wv);
    float* Dst = (which == 0) ? g_Q : (which == 1 ? g_K : g_V);
    const int n0 = (nblk & 7) * 128;
    const int m0 = blockIdx.y * 128;

    const int tid = threadIdx.x;
    const int lane = tid & 31, wid = tid >> 5;
    const int wm = wid >> 2, wn = wid & 3;
    const int g = lane >> 2, t = lane & 3;

    float acc[4][4][4] = {};
    tf32_mainloop(X, W, m0, n0, tid, As, Bs, acc);

#pragma unroll
    for (int mt = 0; mt < 4; mt++) {
        int m = m0 + wm * 64 + mt * 16 + g;
        int b = m >> 11, s = m & (SS - 1);
#pragma unroll
        for (int nt = 0; nt < 4; nt++) {
            int n = n0 + wn * 32 + nt * 8 + 2 * t;
            int h = n >> 6, d = n & 63;
            float* dst = &Dst[(((b * HH + h) * SS) + s) * DD + d];
            *(float2*)dst = make_float2(acc[mt][nt][0], acc[mt][nt][1]);
            *(float2*)(dst + 8 * DD) = make_float2(acc[mt][nt][2], acc[mt][nt][3]);
        }
    }
}

// ---------------------------------------------------------------------------
// Output projection (TF32): out = ctx @ Wo^T + bo
// ---------------------------------------------------------------------------
__global__ __launch_bounds__(256, 2) void out_gemm(
    const float* __restrict__ Wo,
    const float* __restrict__ bo,
    float* __restrict__ out)
{
    extern __shared__ float gsm[];
    float (*As)[36] = (float(*)[36])gsm;
    float (*Bs)[36] = (float(*)[36])(gsm + 2 * 128 * 36);

    const int n0 = blockIdx.x * 128;
    const int m0 = blockIdx.y * 128;

    const int tid = threadIdx.x;
    const int lane = tid & 31, wid = tid >> 5;
    const int wm = wid >> 2, wn = wid & 3;
    const int g = lane >> 2, t = lane & 3;

    float acc[4][4][4] = {};
    tf32_mainloop(g_ctx, Wo, m0, n0, tid, As, Bs, acc);

#pragma unroll
    for (int nt = 0; nt < 4; nt++) {
        int n = n0 + wn * 32 + nt * 8 + 2 * t;
        float2 bias = *(const float2*)&bo[n];
#pragma unroll
        for (int mt = 0; mt < 4; mt++) {
            int m = m0 + wm * 64 + mt * 16 + g;
            *(float2*)&out[m * 1024 + n] =
                make_float2(acc[mt][nt][0] + bias.x, acc[mt][nt][1] + bias.y);
            *(float2*)&out[(m + 8) * 1024 + n] =
                make_float2(acc[mt][nt][2] + bias.x, acc[mt][nt][3] + bias.y);
        }
    }
}

// ---------------------------------------------------------------------------
// Flash attention, TF32 tensor cores (unchanged from R14).
// ---------------------------------------------------------------------------
#define BR 128
#define BC 64
#define FST 68
#define ATTN_SMEM ((BR*FST + 2*BC*FST + BR*FST) * 4)

__global__ __launch_bounds__(256, 2) void flash_attn()
{
    extern __shared__ unsigned smu[];
    unsigned (*Qs)[FST] = (unsigned(*)[FST])smu;
    unsigned (*Ks)[FST] = (unsigned(*)[FST])(smu + BR * FST);
    unsigned (*Vs)[FST] = (unsigned(*)[FST])(smu + (BR + BC) * FST);
    unsigned (*Ps)[FST] = (unsigned(*)[FST])(smu + (BR + 2 * BC) * FST);

    const int bh = blockIdx.y;
    const int qt = (SS / BR - 1) - blockIdx.x;   // longest-job-first
    const int q0 = qt * BR;
    const float* Qg = g_Q + bh * SS * DD;
    const float* Kg = g_K + bh * SS * DD;
    const float* Vg = g_V + bh * SS * DD;

    const int tid = threadIdx.x;
    const int lane = tid & 31, w = tid >> 5;
    const int g = lane >> 2, t = lane & 3;
    const int wr = w * 16;

#pragma unroll
    for (int it = 0; it < 8; it++) {
        int idx = tid + it * 256;
        int r = idx >> 4, d0 = (idx & 15) * 4;
        float4 v = *(const float4*)&Qg[(q0 + r) * DD + d0];
        *(uint4*)&Qs[r][d0] = make_uint4(f2tf(0.125f * v.x), f2tf(0.125f * v.y),
                                         f2tf(0.125f * v.z), f2tf(0.125f * v.w));
    }

    float oacc[8][4] = {};
    float m0 = -1e30f, m1 = -1e30f, l0 = 0.f, l1 = 0.f;

    const int jmax = 2 * qt + 1;
    for (int jt = 0; jt <= jmax; jt++) {
        const int j0 = jt * BC;
        __syncthreads();
#pragma unroll
        for (int it = 0; it < 4; it++) {
            int idx = tid + it * 256;
            int r = idx >> 4, d0 = (idx & 15) * 4;
            float4 kv = *(const float4*)&Kg[(j0 + r) * DD + d0];
            *(uint4*)&Ks[r][d0] = make_uint4(f2tf(kv.x), f2tf(kv.y), f2tf(kv.z), f2tf(kv.w));
            float4 vv = *(const float4*)&Vg[(j0 + r) * DD + d0];
            *(uint4*)&Vs[r][d0] = make_uint4(f2tf(vv.x), f2tf(vv.y), f2tf(vv.z), f2tf(vv.w));
        }
        __syncthreads();

        if (j0 <= q0 + wr + 15) {
            float sacc[8][4] = {};
#pragma unroll
            for (int ks = 0; ks < 8; ks++) {
                const int k0 = ks * 8;
                unsigned a0 = Qs[wr + g][k0 + t];
                unsigned a1 = Qs[wr + g + 8][k0 + t];
                unsigned a2 = Qs[wr + g][k0 + t + 4];
                unsigned a3 = Qs[wr + g + 8][k0 + t + 4];
#pragma unroll
                for (int nt = 0; nt < 8; nt++) {
                    unsigned b0 = Ks[nt * 8 + g][k0 + t];
                    unsigned b1 = Ks[nt * 8 + g][k0 + t + 4];
                    mma_tf32(sacc[nt], a0, a1, a2, a3, b0, b1);
                }
            }

            const int r0 = q0 + wr + g, r1 = r0 + 8;
            if (j0 + BC - 1 > q0 + wr) {
#pragma unroll
                for (int nt = 0; nt < 8; nt++) {
                    int c0 = j0 + nt * 8 + 2 * t, c1 = c0 + 1;
                    if (c0 > r0) sacc[nt][0] = -1e30f;
                    if (c1 > r0) sacc[nt][1] = -1e30f;
                    if (c0 > r1) sacc[nt][2] = -1e30f;
                    if (c1 > r1) sacc[nt][3] = -1e30f;
                }
            }

            float mx0 = -1e30f, mx1 = -1e30f;
#pragma unroll
            for (int nt = 0; nt < 8; nt++) {
                mx0 = fmaxf(mx0, fmaxf(sacc[nt][0], sacc[nt][1]));
                mx1 = fmaxf(mx1, fmaxf(sacc[nt][2], sacc[nt][3]));
            }
            mx0 = fmaxf(mx0, __shfl_xor_sync(0xffffffffu, mx0, 1));
            mx0 = fmaxf(mx0, __shfl_xor_sync(0xffffffffu, mx0, 2));
            mx1 = fmaxf(mx1, __shfl_xor_sync(0xffffffffu, mx1, 1));
            mx1 = fmaxf(mx1, __shfl_xor_sync(0xffffffffu, mx1, 2));
            float mn0 = fmaxf(m0, mx0), mn1 = fmaxf(m1, mx1);
            float a0 = __expf(m0 - mn0), a1 = __expf(m1 - mn1);
            m0 = mn0; m1 = mn1;

            float rs0 = 0.f, rs1 = 0.f;
#pragma unroll
            for (int nt = 0; nt < 8; nt++) {
                float p0 = __expf(sacc[nt][0] - mn0);
                float p1 = __expf(sacc[nt][1] - mn0);
                float p2 = __expf(sacc[nt][2] - mn1);
                float p3 = __expf(sacc[nt][3] - mn1);
                rs0 += p0 + p1; rs1 += p2 + p3;
                *(uint2*)&Ps[wr + g][nt * 8 + 2 * t] = make_uint2(f2tf(p0), f2tf(p1));
                *(uint2*)&Ps[wr + g + 8][nt * 8 + 2 * t] = make_uint2(f2tf(p2), f2tf(p3));
                oacc[nt][0] *= a0; oacc[nt][1] *= a0;
                oacc[nt][2] *= a1; oacc[nt][3] *= a1;
            }
            rs0 += __shfl_xor_sync(0xffffffffu, rs0, 1);
            rs0 += __shfl_xor_sync(0xffffffffu, rs0, 2);
            rs1 += __shfl_xor_sync(0xffffffffu, rs1, 1);
            rs1 += __shfl_xor_sync(0xffffffffu, rs1, 2);
            l0 = l0 * a0 + rs0;
            l1 = l1 * a1 + rs1;

            __syncwarp();

#pragma unroll
            for (int ks = 0; ks < 8; ks++) {
                const int k0 = ks * 8;
                unsigned pa0 = Ps[wr + g][k0 + t];
                unsigned pa1 = Ps[wr + g + 8][k0 + t];
                unsigned pa2 = Ps[wr + g][k0 + t + 4];
                unsigned pa3 = Ps[wr + g + 8][k0 + t + 4];
#pragma unroll
                for (int nt = 0; nt < 8; nt++) {
                    unsigned b0 = Vs[k0 + t][nt * 8 + g];
                    unsigned b1 = Vs[k0 + t + 4][nt * 8 + g];
                    mma_tf32(oacc[nt], pa0, pa1, pa2, pa3, b0, b1);
                }
            }
        }
    }

    const int b = bh >> 4, h = bh & 15;
    const float inv0 = 1.0f / l0, inv1 = 1.0f / l1;
    const int r0 = q0 + wr + g, r1 = r0 + 8;
#pragma unroll
    for (int nt = 0; nt < 8; nt++) {
        int col = h * DD + nt * 8 + 2 * t;
        *(float2*)&g_ctx[(b * SS + r0) * (HH * DD) + col] =
            make_float2(oacc[nt][0] * inv0, oacc[nt][1] * inv0);
        *(float2*)&g_ctx[(b * SS + r1) * (HH * DD) + col] =
            make_float2(oacc[nt][2] * inv1, oacc[nt][3] * inv1);
    }
}

// ---------------------------------------------------------------------------
extern "C" void kernel_launch(void* const* d_in, const int* in_sizes, int n_in,
                              void* d_out, int out_size)
{
    const float* x  = (const float*)d_in[0];
    const float* wq = (const float*)d_in[2];
    const float* wk = (const float*)d_in[3];
    const float* wv = (const float*)d_in[4];
    const float* wo = (const float*)d_in[5];
    const float* bo = (const float*)d_in[6];
    float* out = (float*)d_out;

    cudaFuncSetAttribute(qkv_gemm,
                         cudaFuncAttributeMaxDynamicSharedMemorySize, GEMM_SMEM);
    cudaFuncSetAttribute(out_gemm,
                         cudaFuncAttributeMaxDynamicSharedMemorySize, GEMM_SMEM);
    cudaFuncSetAttribute(flash_attn,
                         cudaFuncAttributeMaxDynamicSharedMemorySize, ATTN_SMEM);

    qkv_gemm<<<dim3(24, 32), 256, GEMM_SMEM>>>(x, wq, wk, wv);
    flash_attn<<<dim3(SS / BR, 32), 256, ATTN_SMEM>>>();
    out_gemm<<<dim3(8, 32), 256, GEMM_SMEM>>>(wo, bo, out);
}